// round 1
// baseline (speedup 1.0000x reference)
#include <cuda_runtime.h>

// Shapes are fixed by the problem: B=4, LQ=4096, LK=4096, D=128.
#define B_  4
#define LQ_ 4096
#define LK_ 4096
#define D_  128

// Scratch (no allocations allowed in kernel_launch).
__device__ float g_s[B_ * LK_];          // raw scores sk[b,j]
__device__ float g_p[B_ * LK_];          // softmax probs p[b,j]
__device__ float g_part[B_ * 16 * D_];   // partial p@V sums
__device__ float g_o[B_ * D_];           // o[b,d]

// ---------------------------------------------------------------------------
// A1: sk[b,j] = dot(key[b,j,:], w_k).  One warp per j; 128 floats = 32 float4,
// exactly one float4 per lane -> fully coalesced, shuffle-reduce.
// ---------------------------------------------------------------------------
__global__ void k_score(const float* __restrict__ key, const float* __restrict__ wk) {
    int gw   = (blockIdx.x * blockDim.x + threadIdx.x) >> 5;  // global warp = (b,j)
    int lane = threadIdx.x & 31;
    if (gw >= B_ * LK_) return;
    float4 a = reinterpret_cast<const float4*>(key)[(long)gw * 32 + lane];
    float4 w = reinterpret_cast<const float4*>(wk)[lane];
    float v = a.x * w.x + a.y * w.y + a.z * w.z + a.w * w.w;
#pragma unroll
    for (int o = 16; o > 0; o >>= 1) v += __shfl_down_sync(0xffffffffu, v, o);
    if (lane == 0) g_s[gw] = v;
}

// ---------------------------------------------------------------------------
// A2: per-batch softmax over LK=4096.  One block per batch, 1024 threads,
// 4 values per thread; fixed-order block reductions (deterministic).
// ---------------------------------------------------------------------------
__global__ void k_softmax() {
    __shared__ float red[1024];
    int b = blockIdx.x, tid = threadIdx.x;
    float sv[4];
#pragma unroll
    for (int k = 0; k < 4; k++) sv[k] = g_s[b * LK_ + tid + k * 1024];
    float lmax = fmaxf(fmaxf(sv[0], sv[1]), fmaxf(sv[2], sv[3]));
    red[tid] = lmax;
    __syncthreads();
    for (int s = 512; s > 0; s >>= 1) {
        if (tid < s) red[tid] = fmaxf(red[tid], red[tid + s]);
        __syncthreads();
    }
    float mx = red[0];
    __syncthreads();
    float e[4], lsum = 0.f;
#pragma unroll
    for (int k = 0; k < 4; k++) { e[k] = __expf(sv[k] - mx); lsum += e[k]; }
    red[tid] = lsum;
    __syncthreads();
    for (int s = 512; s > 0; s >>= 1) {
        if (tid < s) red[tid] += red[tid + s];
        __syncthreads();
    }
    float inv = 1.0f / red[0];
#pragma unroll
    for (int k = 0; k < 4; k++) g_p[b * LK_ + tid + k * 1024] = e[k] * inv;
}

// ---------------------------------------------------------------------------
// A3: partial o: each block (chunk c of 256 j's, batch b) accumulates
// acc[d] = sum_{j in chunk} p[j] * val[b,j,d].  128 threads = one per d,
// val loads coalesced across d. Deterministic order.
// ---------------------------------------------------------------------------
__global__ void k_pv_partial(const float* __restrict__ val) {
    int b = blockIdx.y, c = blockIdx.x, d = threadIdx.x;
    const float* pv = g_p + b * LK_ + c * 256;
    const float* v  = val + ((long)(b * LK_ + c * 256)) * D_ + d;
    float acc = 0.f;
#pragma unroll 4
    for (int j = 0; j < 256; j++) acc = fmaf(pv[j], v[(long)j * D_], acc);
    g_part[(b * 16 + c) * D_ + d] = acc;
}

// A4: reduce the 16 partials per (b,d).
__global__ void k_pv_final() {
    int idx = threadIdx.x;           // 512 = B*D/... (B_*D_ = 512)
    int b = idx >> 7, d = idx & 127;
    float acc = 0.f;
#pragma unroll
    for (int c = 0; c < 16; c++) acc += g_part[(b * 16 + c) * D_ + d];
    g_o[idx] = acc;
}

// ---------------------------------------------------------------------------
// B1: broadcast out[b,i,:] = o[b,:].  2M floats = 8 MB, float4 stores.
// ---------------------------------------------------------------------------
__global__ void k_bcast_out(float4* __restrict__ out) {
    int i  = blockIdx.x * blockDim.x + threadIdx.x;  // over B*LQ*D/4 = 524288
    int d4 = i & 31;                                  // D/4 = 32
    int b  = i >> 17;                                 // LQ*D/4 = 131072 = 2^17
    float4 v = reinterpret_cast<const float4*>(g_o)[b * 32 + d4];
    out[i] = v;
}

// ---------------------------------------------------------------------------
// B2: broadcast att[b,i,:] = p[b,:].  256 MB of streaming writes (dominant).
// p is 64 KB total -> L1/L2 resident; use streaming stores for att.
// ---------------------------------------------------------------------------
__global__ void k_bcast_att(float4* __restrict__ att) {
    const long n4     = (long)B_ * LQ_ * LK_ / 4;     // 16,777,216
    const long stride = (long)gridDim.x * blockDim.x;
    for (long i = blockIdx.x * (long)blockDim.x + threadIdx.x; i < n4; i += stride) {
        int j4 = (int)(i & 1023);                     // LK/4 = 1024
        int b  = (int)(i >> 22);                      // LQ*LK/4 = 2^22
        float4 v = reinterpret_cast<const float4*>(g_p)[b * 1024 + j4];
        __stcs(att + i, v);
    }
}

extern "C" void kernel_launch(void* const* d_in, const int* in_sizes, int n_in,
                              void* d_out, int out_size) {
    // inputs: 0=qry (unused), 1=key, 2=val, 3=w_q (unused), 4=w_k
    const float* key = (const float*)d_in[1];
    const float* val = (const float*)d_in[2];
    const float* wk  = (const float*)d_in[4];
    float* out = (float*)d_out;

    const long OUT_E = (long)B_ * LQ_ * D_;   // 2,097,152
    const long ATT_E = (long)B_ * LQ_ * LK_;  // 67,108,864

    k_score<<<(B_ * LK_) / 8, 256>>>(key, wk);   // 8 warps/block
    k_softmax<<<B_, 1024>>>();
    dim3 g3(16, B_);
    k_pv_partial<<<g3, 128>>>(val);
    k_pv_final<<<1, 512>>>();

    float* out_ptr = nullptr;
    float* att_ptr = nullptr;
    if ((long)out_size >= OUT_E + ATT_E) {        // (out, att) concatenated
        out_ptr = out;
        att_ptr = out + OUT_E;
    } else if ((long)out_size == ATT_E) {         // att only
        att_ptr = out;
    } else {                                      // out only
        out_ptr = out;
    }

    if (out_ptr) k_bcast_out<<<(int)(OUT_E / 4 / 256), 256>>>((float4*)out_ptr);
    if (att_ptr) k_bcast_att<<<4096, 256>>>((float4*)att_ptr);
}

// round 2
// speedup vs baseline: 1.1502x; 1.1502x over previous
#include <cuda_runtime.h>
#include <math_constants.h>

// Shapes fixed: B=4, LQ=4096, LK=4096, D=128.
#define B_  4
#define LQ_ 4096
#define LK_ 4096
#define D_  128

// Scratch (no allocations allowed).
__device__ float g_s[B_ * LK_];           // raw scores sk[b,j]
__device__ float g_p[B_ * LK_];           // softmax probs
__device__ float g_bm[2048];              // per-score-block max   (512 per batch)
__device__ float g_bs[2048];              // per-score-block sumexp
__device__ float g_M[B_];                 // global max per batch
__device__ float g_invS[B_];              // 1/sum per batch
__device__ float g_part[B_ * 32 * D_];    // 32 p@V partials per batch

// ---------------------------------------------------------------------------
// K1: scores + per-block softmax stats.
// Warp per j (32 float4 = one per lane, coalesced). 8 warps/block.
// Block also emits (max, sum exp(v-max)) over its 8 scores.
// ---------------------------------------------------------------------------
__global__ void k_score(const float* __restrict__ key, const float* __restrict__ wk) {
    __shared__ float sv[8];
    int gw   = (blockIdx.x * 256 + threadIdx.x) >> 5;   // (b,j), grid covers exactly B*LK
    int lane = threadIdx.x & 31;
    int w    = threadIdx.x >> 5;
    float4 a = reinterpret_cast<const float4*>(key)[(long)gw * 32 + lane];
    float4 q = reinterpret_cast<const float4*>(wk)[lane];
    float v = a.x * q.x + a.y * q.y + a.z * q.z + a.w * q.w;
#pragma unroll
    for (int o = 16; o > 0; o >>= 1) v += __shfl_down_sync(0xffffffffu, v, o);
    if (lane == 0) { g_s[gw] = v; sv[w] = v; }
    __syncthreads();
    if (threadIdx.x < 32) {
        float m = (lane < 8) ? sv[lane] : -CUDART_INF_F;
#pragma unroll
        for (int o = 16; o > 0; o >>= 1) m = fmaxf(m, __shfl_xor_sync(0xffffffffu, m, o));
        float e = (lane < 8) ? __expf(sv[lane] - m) : 0.f;
#pragma unroll
        for (int o = 16; o > 0; o >>= 1) e += __shfl_xor_sync(0xffffffffu, e, o);
        if (lane == 0) { g_bm[blockIdx.x] = m; g_bs[blockIdx.x] = e; }
    }
}

// ---------------------------------------------------------------------------
// K2: combine 512 block-stats per batch -> (M, 1/S). 4 blocks x 512 threads,
// pure shuffle reduction with online rescale.
// ---------------------------------------------------------------------------
__device__ __forceinline__ void stat_combine(float& m, float& s, float m2, float s2) {
    float M = fmaxf(m, m2);
    s = s * __expf(m - M) + s2 * __expf(m2 - M);
    m = M;
}

__global__ void k_combine() {
    __shared__ float sm[16], ss[16];
    int b = blockIdx.x, tid = threadIdx.x;
    int lane = tid & 31, w = tid >> 5;
    float m = g_bm[b * 512 + tid];
    float s = g_bs[b * 512 + tid];
#pragma unroll
    for (int o = 16; o > 0; o >>= 1)
        stat_combine(m, s, __shfl_xor_sync(0xffffffffu, m, o),
                           __shfl_xor_sync(0xffffffffu, s, o));
    if (lane == 0) { sm[w] = m; ss[w] = s; }
    __syncthreads();
    if (tid < 32) {
        m = (tid < 16) ? sm[tid] : -CUDART_INF_F;
        s = (tid < 16) ? ss[tid] : 0.f;
#pragma unroll
        for (int o = 16; o > 0; o >>= 1)
            stat_combine(m, s, __shfl_xor_sync(0xffffffffu, m, o),
                               __shfl_xor_sync(0xffffffffu, s, o));
        if (tid == 0) { g_M[b] = m; g_invS[b] = 1.0f / s; }
    }
}

// ---------------------------------------------------------------------------
// K3: fused p + p@V partial. Block = (chunk c of 128 j, batch b), 128 threads.
// Computes p for its chunk (writes g_p + smem), then acc[d] = sum p[j]*val[j,d].
// ---------------------------------------------------------------------------
__global__ void k_pv(const float* __restrict__ val) {
    __shared__ float sp[128];
    int b = blockIdx.y, c = blockIdx.x, d = threadIdx.x;
    int j0 = b * LK_ + c * 128;
    float p = __expf(g_s[j0 + d] - g_M[b]) * g_invS[b];
    sp[d] = p;
    g_p[j0 + d] = p;
    __syncthreads();
    const float* v = val + (long)j0 * D_ + d;
    float acc = 0.f;
#pragma unroll 8
    for (int j = 0; j < 128; j++) acc = fmaf(sp[j], v[(long)j * D_], acc);
    g_part[(b * 32 + c) * D_ + d] = acc;
}

// ---------------------------------------------------------------------------
// K4: att broadcast — 256 MB of streaming writes (dominant).
// Grid-stride = 2^20 float4 (multiple of 1024) => j4 fixed per thread, only b
// varies; hoist the 4 p-vectors into registers, then 16 pure __stcs stores.
// ---------------------------------------------------------------------------
__global__ void k_att(float4* __restrict__ att) {
    int t  = blockIdx.x * 256 + threadIdx.x;   // 4096 blocks -> 2^20 threads
    int j4 = t & 1023;                          // LK/4
    const float4* p4 = reinterpret_cast<const float4*>(g_p);
    float4 v0 = p4[j4];
    float4 v1 = p4[1024 + j4];
    float4 v2 = p4[2048 + j4];
    float4 v3 = p4[3072 + j4];
    long i = t;
#pragma unroll
    for (int k = 0; k < 16; k++) {
        float4 v = (k < 4) ? v0 : (k < 8) ? v1 : (k < 12) ? v2 : v3;
        __stcs(att + i, v);
        i += (1L << 20);
    }
}

// ---------------------------------------------------------------------------
// K5: out broadcast with folded partial-reduce. Block = 16 rows of one batch,
// 128 threads: each thread reduces 32 float4 partials (L2-resident) for its
// d4, then writes 4 rows' worth of float4.
// ---------------------------------------------------------------------------
__global__ void k_out(float4* __restrict__ out) {
    int blk = blockIdx.x;              // 1024 = B * (LQ/16)
    int b   = blk >> 8;
    int r0  = (blk & 255) * 16;
    int t   = threadIdx.x;
    int d4  = t & 31, rg = t >> 5;
    const float4* part = reinterpret_cast<const float4*>(g_part) + (b * 32) * 32 + d4;
    float4 acc = make_float4(0.f, 0.f, 0.f, 0.f);
#pragma unroll
    for (int c = 0; c < 32; c++) {
        float4 q = part[c * 32];
        acc.x += q.x; acc.y += q.y; acc.z += q.z; acc.w += q.w;
    }
    float4* o = out + ((long)b * LQ_ + r0) * 32 + d4;
#pragma unroll
    for (int k = 0; k < 4; k++) o[(rg + k * 4) * 32] = acc;
}

extern "C" void kernel_launch(void* const* d_in, const int* in_sizes, int n_in,
                              void* d_out, int out_size) {
    // inputs: 0=qry (dead), 1=key, 2=val, 3=w_q (dead), 4=w_k
    const float* key = (const float*)d_in[1];
    const float* val = (const float*)d_in[2];
    const float* wk  = (const float*)d_in[4];
    float* out = (float*)d_out;

    const long OUT_E = (long)B_ * LQ_ * D_;   // 2,097,152
    const long ATT_E = (long)B_ * LQ_ * LK_;  // 67,108,864

    float* out_ptr = nullptr;
    float* att_ptr = nullptr;
    if ((long)out_size >= OUT_E + ATT_E) { out_ptr = out; att_ptr = out + OUT_E; }
    else if ((long)out_size == ATT_E)    { att_ptr = out; }
    else                                 { out_ptr = out; }

    k_score<<<(B_ * LK_) / 8, 256>>>(key, wk);
    k_combine<<<B_, 512>>>();
    if (out_ptr) {
        dim3 g3(32, B_);
        k_pv<<<g3, 128>>>(val);
    }
    if (att_ptr) k_att<<<4096, 256>>>((float4*)att_ptr);
    if (out_ptr) k_out<<<1024, 128>>>((float4*)out_ptr);
}